// round 14
// baseline (speedup 1.0000x reference)
#include <cuda_runtime.h>
#include <cuda_fp16.h>
#include <cstdint>
#include <math.h>

#define Bsz   4096
#define Dd    256
#define Ccls  10
#define Nrows 8192
#define TILES 64          // 8192 / 128
#define NBLK  2080        // 64*65/2 triangular tiles
#define PGRID 296         // persistent CTAs (2 per SM x 148)

// ===================== device scratch ====================================
__device__ __align__(16) __half g_xh[4][Nrows][64];
__device__ float g_sq[Nrows];
__device__ float g_spart[128][Ccls];
__device__ float g_tpart[128][Ccls];
__device__ int   g_cpart[128][Ccls];
__device__ __align__(16) float g_vpartT[256][256]; // TRANSPOSED column sums
__device__ float g_qpart[256];
__device__ float g_sscale[Ccls];
__device__ float g_tscale[Ccls];
__device__ float g_expC;              // log2e/(4*bw_raw)  (exp2 domain)
__device__ float g_invcount;
__device__ unsigned g_ctr;            // last-block counter (monotonic)

// ---------------- helpers -------------------------------------------------
__device__ __forceinline__ void mma_f16(float* d, const uint32_t* a, const uint32_t* b) {
    asm volatile(
        "mma.sync.aligned.m16n8k16.row.col.f32.f16.f16.f32 "
        "{%0,%1,%2,%3}, {%4,%5,%6,%7}, {%8,%9}, {%0,%1,%2,%3};"
        : "+f"(d[0]), "+f"(d[1]), "+f"(d[2]), "+f"(d[3])
        : "r"(a[0]), "r"(a[1]), "r"(a[2]), "r"(a[3]), "r"(b[0]), "r"(b[1]));
}
__device__ __forceinline__ void ldsm_x4(uint32_t* r, uint32_t addr) {
    asm volatile("ldmatrix.sync.aligned.m8n8.x4.shared.b16 {%0,%1,%2,%3}, [%4];"
        : "=r"(r[0]), "=r"(r[1]), "=r"(r[2]), "=r"(r[3]) : "r"(addr));
}
__device__ __forceinline__ uint32_t smem_u32(const void* p) {
    return (uint32_t)__cvta_generic_to_shared(p);
}
__device__ __forceinline__ float ex2(float x) {
    float r;
    asm("ex2.approx.ftz.f32 %0, %1;" : "=f"(r) : "f"(x));
    return r;
}
#define MBAR_INIT(mbar, cnt) \
    asm volatile("mbarrier.init.shared.b64 [%0], %1;" \
                 :: "r"((uint32_t)(mbar)), "r"((uint32_t)(cnt)) : "memory")
#define MBAR_EXPECT_TX(mbar, bytes) \
    asm volatile("mbarrier.arrive.expect_tx.shared.b64 _, [%0], %1;" \
                 :: "r"((uint32_t)(mbar)), "r"((uint32_t)(bytes)) : "memory")
#define BULK_G2S(dst, src, bytes, mbar) \
    asm volatile("cp.async.bulk.shared::cluster.global.mbarrier::complete_tx::bytes " \
                 "[%0], [%1], %2, [%3];" \
                 :: "r"((uint32_t)(dst)), "l"(src), "r"((uint32_t)(bytes)), \
                    "r"((uint32_t)(mbar)) : "memory")
#define MBAR_WAIT(mbar, parity) do {                                             \
    uint32_t _m = (uint32_t)(mbar); uint32_t _p = (uint32_t)(parity);            \
    uint32_t _done;                                                              \
    asm volatile("{\n\t.reg .pred p;\n\t"                                        \
        "mbarrier.try_wait.parity.acquire.cta.shared::cta.b64 p, [%1], %2;\n\t"  \
        "selp.b32 %0, 1, 0, p;\n\t}" : "=r"(_done) : "r"(_m), "r"(_p) : "memory"); \
    if (!_done) {                                                                \
        asm volatile("{\n\t.reg .pred P1;\n\t"                                   \
            "W_%=:\n\t"                                                          \
            "mbarrier.try_wait.parity.acquire.cta.shared::cta.b64 P1, [%0], %1, 0x989680;\n\t" \
            "@P1 bra.uni D_%=;\n\tbra.uni W_%=;\n\tD_%=:\n\t}"                   \
            :: "r"(_m), "r"(_p) : "memory");                                     \
    }                                                                            \
} while (0)

// ---------------- kernel 1: rows + stats + (last block) finalize ----------
// 256 blocks x 256 threads; block = 32 rows (R13-proven).
__global__ void k_row(const float* __restrict__ src,
                      const float* __restrict__ tgt,
                      const float* __restrict__ slab,
                      const float* __restrict__ tlog,
                      float* __restrict__ out) {
    __shared__ float scol[8][256];
    __shared__ float bs[8];
    __shared__ int   lastFlag;
    int tid = threadIdx.x;
    int w = tid >> 5, lane = tid & 31;
    int bid = blockIdx.x;

    if (w == 0) {
        int r = bid * 32 + lane;
        float val[Ccls];
        int bx = 0;
        if (bid < 128) {
            #pragma unroll
            for (int c = 0; c < Ccls; c++) val[c] = slab[(size_t)r * Ccls + c];
        } else {
            int rr = r - Bsz;
            float best = -1.f;
            #pragma unroll
            for (int c = 0; c < Ccls; c++) {
                val[c] = tlog[(size_t)rr * Ccls + c];
                if (val[c] > best) { best = val[c]; bx = c; }
            }
        }
        #pragma unroll
        for (int c = 0; c < Ccls; c++) {
            float x = val[c];
            #pragma unroll
            for (int o = 16; o; o >>= 1) x += __shfl_xor_sync(0xffffffffu, x, o);
            int cc = __popc(__ballot_sync(0xffffffffu, bx == c));
            if (lane == 0) {
                if (bid < 128) g_spart[bid][c] = x;
                else { g_tpart[bid - 128][c] = x; g_cpart[bid - 128][c] = cc; }
            }
        }
    }

    float2 colacc[4];
    #pragma unroll
    for (int i = 0; i < 4; i++) colacc[i] = make_float2(0.f, 0.f);
    float wsq = 0.f;
    int c0 = 2 * lane;
    int uu = c0 >> 3, oo = c0 & 7;
    #pragma unroll
    for (int k = 0; k < 4; k++) {
        int row = bid * 32 + w * 4 + k;
        const float* p = (row < Bsz) ? src + (size_t)row * Dd
                                     : tgt + (size_t)(row - Bsz) * Dd;
        int rx = row & 7;
        int sw = (((uu ^ rx) << 3) | oo);
        float s = 0.f;
        #pragma unroll
        for (int i = 0; i < 4; i++) {
            float2 v = *(const float2*)(p + c0 + 64 * i);
            s += v.x * v.x + v.y * v.y;
            colacc[i].x += v.x; colacc[i].y += v.y;
            *(__half2*)&g_xh[i][row][sw] = __floats2half2_rn(v.x, v.y);
        }
        #pragma unroll
        for (int o = 16; o; o >>= 1) s += __shfl_xor_sync(0xffffffffu, s, o);
        if (lane == 0) { g_sq[row] = s; wsq += s; }
    }
    #pragma unroll
    for (int i = 0; i < 4; i++) *(float2*)&scol[w][c0 + 64 * i] = colacc[i];
    if (lane == 0) bs[w] = wsq;
    __syncthreads();
    float cs = 0.f;
    #pragma unroll
    for (int ww = 0; ww < 8; ww++) cs += scol[ww][tid];
    g_vpartT[tid][bid] = cs;
    if (tid == 0) {
        float tot = 0.f;
        #pragma unroll
        for (int i = 0; i < 8; i++) tot += bs[i];
        g_qpart[bid] = tot;
    }

    __threadfence();
    if (tid == 0) {
        unsigned old = atomicAdd(&g_ctr, 1u);
        lastFlag = (((old + 1u) & 255u) == 0u);
    }
    __syncthreads();
    if (!lastFlag) return;

    __shared__ float red[256];
    __shared__ float ssumS[Ccls];
    __shared__ int   cntS[Ccls];
    int t = tid;
    if (t < Ccls) {
        float ss = 0.f, ts = 0.f; int cc = 0;
        #pragma unroll 4
        for (int b2 = 0; b2 < 128; b2++) {
            ss += g_spart[b2][t];
            ts += g_tpart[b2][t];
            cc += g_cpart[b2][t];
        }
        ssumS[t] = ss; cntS[t] = cc;
        bool mask = (ss > 0.f) && (cc > 0);
        g_sscale[t] = mask ? (1.f / ss) : 0.f;
        float te = (ts == 0.f) ? 100.f : ts;
        g_tscale[t] = mask ? (-1.f / te) : 0.f;
    }
    float v = 0.f;
    {
        const float4* vp = (const float4*)&g_vpartT[t][0];
        #pragma unroll 16
        for (int i = 0; i < 64; i++) {
            float4 x = vp[i];
            v += (x.x + x.y) + (x.z + x.w);
        }
    }
    red[t] = v * v;
    __syncthreads();
    for (int s = 128; s; s >>= 1) { if (t < s) red[t] += red[t + s]; __syncthreads(); }
    float VV = red[0];
    __syncthreads();
    red[t] = g_qpart[t];
    __syncthreads();
    for (int s = 128; s; s >>= 1) { if (t < s) red[t] += red[t + s]; __syncthreads(); }
    if (t == 0) {
        int count = 0;
        for (int c = 0; c < Ccls; c++)
            if (ssumS[c] > 0.f && cntS[c] > 0) count++;
        float S = red[0];
        float sum_l2 = 2.f * (float)Nrows * S - 2.f * VV;
        float nf = (float)Nrows;
        float bw_raw = sum_l2 / (nf * nf - nf);
        g_expC = 1.44269504088896f / (4.f * bw_raw);
        g_invcount = (count > 0) ? 1.f / (float)count : 0.f;
        out[0] = 0.f;
    }
}

// ---------------- kernel 2: PERSISTENT fp16 mma GEMM + MMD epilogue -------
// 296 persistent CTAs; each processes tiles bid, bid+296, ... The 3-stage
// bulk-async ring rolls across tile boundaries: next tile's chunks are
// issued during the current tile's epilogue, hiding the cold-start wait.
#define NSTAGE  3
#define STAGEB  32768
#define OFF_BUF 0
#define OFF_MBAR (NSTAGE * STAGEB)
#define OFF_UPH (OFF_MBAR + 64)         // [128][24] halves, 48B stride
#define OFF_UQH (OFF_UPH + 128 * 48)
#define OFF_SQP (OFF_UQH + 128 * 48)
#define OFF_SQQ (OFF_SQP + 512)
#define OFF_RED (OFF_SQQ + 512)
#define SMEM_DYN (OFF_RED + 64)

__device__ __forceinline__ void decode_tile(int b, int& bi, int& bj) {
    int i = (int)((2.f * TILES + 1.f -
                   sqrtf((float)((2 * TILES + 1) * (2 * TILES + 1) - 8 * b))) * 0.5f);
    if (i < 0) i = 0; if (i > TILES - 1) i = TILES - 1;
    while (i > 0 && i * TILES - i * (i - 1) / 2 > b) i--;
    while ((i + 1) * TILES - (i + 1) * i / 2 <= b) i++;
    bi = i; bj = i + (b - (i * TILES - i * (i - 1) / 2));
}

__global__ void __launch_bounds__(256, 2) k_main(
    const float* __restrict__ slab, const float* __restrict__ tlog,
    float* __restrict__ out)
{
    extern __shared__ char sm[];
    float* sqP = (float*)(sm + OFF_SQP);
    float* sqQ = (float*)(sm + OFF_SQQ);
    float* red = (float*)(sm + OFF_RED);
    uint32_t smb = smem_u32(sm);

    int tid = threadIdx.x;
    int w = tid >> 5, lane = tid & 31;
    int g = lane >> 2, t4 = lane & 3;
    int wr = w >> 2, wc = w & 3;

    // ---- mbar init ----
    if (tid == 0) {
        #pragma unroll
        for (int s = 0; s < NSTAGE; s++) MBAR_INIT(smb + OFF_MBAR + 8 * s, 1);
    }
    __syncthreads();

    // ---- first tile decode + prefetch chunks 0-2 ----
    int tile = blockIdx.x;
    int bi, bj;
    decode_tile(tile, bi, bj);
    int p0 = bi * 128, q0 = bj * 128;

    int pst = 0, pph = 0;                 // producer ring position (tid 0)
    if (tid == 0) {
        #pragma unroll
        for (int s = 0; s < 3; s++) {
            uint32_t mb = smb + OFF_MBAR + 8 * pst;
            uint32_t dst = smb + OFF_BUF + pst * STAGEB;
            MBAR_EXPECT_TX(mb, 2 * 16384);
            BULK_G2S(dst,          &g_xh[s][p0][0], 16384, mb);
            BULK_G2S(dst + 16384u, &g_xh[s][q0][0], 16384, mb);
            if (++pst == NSTAGE) { pst = 0; pph ^= 1; }
        }
    }

    // ---- stage u/sq for a tile (all threads) ----
    #define STAGE_U(P0, Q0) do {                                              \
        int half_ = tid >> 7;                                                 \
        int j = tid & 127;                                                    \
        int rr = (half_ ? (Q0) : (P0)) + j;                                   \
        uint32_t uoff = (half_ ? OFF_UQH : OFF_UPH) + (uint32_t)j * 48u;      \
        __half2* d = (__half2*)(sm + uoff);                                   \
        if (half_) sqQ[j] = g_sq[rr]; else sqP[j] = g_sq[rr];                 \
        const float* base_;                                                   \
        const float* scl_;                                                    \
        if (rr < Bsz) { base_ = slab + (size_t)rr * Ccls; scl_ = g_sscale; }  \
        else          { base_ = tlog + (size_t)(rr - Bsz) * Ccls; scl_ = g_tscale; } \
        _Pragma("unroll")                                                     \
        for (int c2 = 0; c2 < 5; c2++) {                                      \
            float a_ = base_[2 * c2]     * scl_[2 * c2]     * 256.f;          \
            float e_ = base_[2 * c2 + 1] * scl_[2 * c2 + 1] * 256.f;          \
            d[c2] = __floats2half2_rn(a_, e_);                                \
        }                                                                     \
        _Pragma("unroll")                                                     \
        for (int c2 = 5; c2 < 12; c2++) d[c2] = __floats2half2_rn(0.f, 0.f);  \
    } while (0)

    STAGE_U(p0, q0);

    // per-lane ldmatrix geometry (invariant)
    uint32_t rx = (uint32_t)(lane & 7);
    uint32_t baseA = (uint32_t)((wr * 64 + (lane & 7) + ((lane >> 3) & 1) * 8) * 128);
    uint32_t hiA = (uint32_t)(lane >> 4);
    uint32_t baseB = (uint32_t)(16384 + (wc * 32 + (lane & 7) + ((lane >> 4) & 1) * 8) * 128);
    uint32_t hiB = (uint32_t)((lane >> 3) & 1);
    uint32_t rowuB = (uint32_t)(wc * 32 + (lane & 7) + ((lane >> 4) & 1) * 8);
    uint32_t addrUB = smb + OFF_UQH + rowuB * 48u + ((uint32_t)((lane >> 3) & 1)) * 16u;

    const float Ce = g_expC;
    const float twoCe = 2.f * Ce;
    const float base_scale = g_invcount * (1.f / 65536.f);

    int st = 0, ph = 0;                   // consumer ring position
    float total = 0.f;

    for (;;) {
        float acc[16][4];
        #pragma unroll
        for (int i = 0; i < 16; i++)
            #pragma unroll
            for (int j = 0; j < 4; j++) acc[i][j] = 0.f;

        // ---- mainloop: 4 chunks ----
        #pragma unroll 1
        for (int ch = 0; ch < 4; ch++) {
            MBAR_WAIT(smb + OFF_MBAR + 8 * st, ph);
            uint32_t bufb = smb + OFF_BUF + st * STAGEB;
            if (++st == NSTAGE) { st = 0; ph ^= 1; }

            uint32_t fA[2][4][4];
            uint32_t fB[2][4][2];
            {
                uint32_t ka = ((hiA ^ rx) << 4);
                uint32_t kb = ((hiB ^ rx) << 4);
                #pragma unroll
                for (int mi = 0; mi < 4; mi++)
                    ldsm_x4(fA[0][mi], bufb + baseA + mi * 2048u + ka);
                #pragma unroll
                for (int np = 0; np < 2; np++)
                    ldsm_x4(&fB[0][2 * np][0], bufb + baseB + np * 2048u + kb);
            }
            #pragma unroll
            for (int ks = 0; ks < 4; ks++) {
                int cur = ks & 1;
                if (ks < 3) {
                    uint32_t kn = (uint32_t)((ks + 1) << 1);
                    uint32_t ka = (((kn | hiA) ^ rx) << 4);
                    uint32_t kb = (((kn | hiB) ^ rx) << 4);
                    #pragma unroll
                    for (int mi = 0; mi < 4; mi++)
                        ldsm_x4(fA[cur ^ 1][mi], bufb + baseA + mi * 2048u + ka);
                    #pragma unroll
                    for (int np = 0; np < 2; np++)
                        ldsm_x4(&fB[cur ^ 1][2 * np][0], bufb + baseB + np * 2048u + kb);
                }
                #pragma unroll
                for (int mi = 0; mi < 4; mi++)
                    #pragma unroll
                    for (int ni = 0; ni < 4; ni++)
                        mma_f16(acc[mi * 4 + ni], fA[cur][mi], fB[cur][ni]);
            }
            if (ch == 0) {
                __syncthreads();          // chunk 0's stage fully consumed
                if (tid == 0) {
                    uint32_t mb = smb + OFF_MBAR + 8 * pst;
                    uint32_t dst = smb + OFF_BUF + pst * STAGEB;
                    MBAR_EXPECT_TX(mb, 2 * 16384);
                    BULK_G2S(dst,          &g_xh[3][p0][0], 16384, mb);
                    BULK_G2S(dst + 16384u, &g_xh[3][q0][0], 16384, mb);
                    if (++pst == NSTAGE) { pst = 0; pph ^= 1; }
                }
            }
        }
        __syncthreads();                  // all stages consumed

        // ---- issue next tile's chunks 0-2 (overlaps epilogue) ----
        int ntile = tile + PGRID;
        bool more = (ntile < NBLK);
        int nbi = 0, nbj = 0, np0 = 0, nq0 = 0;
        if (more) {
            decode_tile(ntile, nbi, nbj);
            np0 = nbi * 128; nq0 = nbj * 128;
            if (tid == 0) {
                #pragma unroll
                for (int s = 0; s < 3; s++) {
                    uint32_t mb = smb + OFF_MBAR + 8 * pst;
                    uint32_t dst = smb + OFF_BUF + pst * STAGEB;
                    MBAR_EXPECT_TX(mb, 2 * 16384);
                    BULK_G2S(dst,          &g_xh[s][np0][0], 16384, mb);
                    BULK_G2S(dst + 16384u, &g_xh[s][nq0][0], 16384, mb);
                    if (++pst == NSTAGE) { pst = 0; pph ^= 1; }
                }
            }
        }

        // ---- epilogue for current tile ----
        const float scale = base_scale * ((bi == bj) ? 1.f : 2.f);
        float partial = 0.f;

        uint32_t fuB[2][4];
        ldsm_x4(fuB[0], addrUB);
        ldsm_x4(fuB[1], addrUB + 16u * 48u);

        #pragma unroll
        for (int mi = 0; mi < 4; mi++) {
            int r0 = wr * 64 + mi * 16 + g;
            int r1 = r0 + 8;
            float spC0 = sqP[r0] * Ce, spC1 = sqP[r1] * Ce;

            uint32_t fuA[4];
            {
                uint32_t rowuA = (uint32_t)(wr * 64 + mi * 16 + (lane & 7) + ((lane >> 3) & 1) * 8);
                ldsm_x4(fuA, smb + OFF_UPH + rowuA * 48u + ((uint32_t)(lane >> 4)) * 16u);
            }
            float wacc[4][4];
            #pragma unroll
            for (int ni = 0; ni < 4; ni++) {
                #pragma unroll
                for (int j = 0; j < 4; j++) wacc[ni][j] = 0.f;
                mma_f16(wacc[ni], fuA, &fuB[ni >> 1][(ni & 1) * 2]);
            }
            #pragma unroll
            for (int ni = 0; ni < 4; ni++) {
                float* a = acc[mi * 4 + ni];
                float* wa = wacc[ni];
                int cbx = wc * 32 + ni * 8 + 2 * t4;
                float2 sv = *(float2*)&sqQ[cbx];
                float svCx = sv.x * Ce, svCy = sv.y * Ce;
                float t, z, z2, z4, z8;
                t = fminf(fmaf(a[0], twoCe, -(spC0 + svCx)), 0.f);
                z = ex2(t); z2 = z * z; z4 = z2 * z2; z8 = z4 * z4;
                partial = fmaf(wa[0], z + z2 + z4 + z8 + z8 * z8, partial);
                t = fminf(fmaf(a[1], twoCe, -(spC0 + svCy)), 0.f);
                z = ex2(t); z2 = z * z; z4 = z2 * z2; z8 = z4 * z4;
                partial = fmaf(wa[1], z + z2 + z4 + z8 + z8 * z8, partial);
                t = fminf(fmaf(a[2], twoCe, -(spC1 + svCx)), 0.f);
                z = ex2(t); z2 = z * z; z4 = z2 * z2; z8 = z4 * z4;
                partial = fmaf(wa[2], z + z2 + z4 + z8 + z8 * z8, partial);
                t = fminf(fmaf(a[3], twoCe, -(spC1 + svCy)), 0.f);
                z = ex2(t); z2 = z * z; z4 = z2 * z2; z8 = z4 * z4;
                partial = fmaf(wa[3], z + z2 + z4 + z8 + z8 * z8, partial);
            }
        }
        total = fmaf(partial, scale, total);

        if (!more) break;
        __syncthreads();                  // epilogue u/sq reads complete
        STAGE_U(np0, nq0);
        tile = ntile; bi = nbi; bj = nbj; p0 = np0; q0 = nq0;
    }

    // ---- final reduction + single atomic per CTA ----
    #pragma unroll
    for (int o = 16; o; o >>= 1) total += __shfl_xor_sync(0xffffffffu, total, o);
    if (lane == 0) red[w] = total;
    __syncthreads();
    if (tid == 0) {
        float s = 0.f;
        #pragma unroll
        for (int i = 0; i < 8; i++) s += red[i];
        atomicAdd(out, s);
    }
    #undef STAGE_U
}

// ---------------- launcher ------------------------------------------------
extern "C" void kernel_launch(void* const* d_in, const int* in_sizes, int n_in,
                              void* d_out, int out_size) {
    const float* src  = (const float*)d_in[0];
    const float* tgt  = (const float*)d_in[1];
    const float* slab = (const float*)d_in[2];
    const float* tlog = (const float*)d_in[3];
    float* out = (float*)d_out;

    static int configured = 0;
    if (!configured) {
        cudaFuncSetAttribute(k_main, cudaFuncAttributeMaxDynamicSharedMemorySize, SMEM_DYN);
        configured = 1;
    }

    k_row<<<256, 256>>>(src, tgt, slab, tlog, out);
    k_main<<<PGRID, 256, SMEM_DYN>>>(slab, tlog, out);
}

// round 16
// speedup vs baseline: 1.0227x; 1.0227x over previous
#include <cuda_runtime.h>
#include <cuda_fp16.h>
#include <cstdint>
#include <math.h>

#define Bsz   4096
#define Dd    256
#define Ccls  10
#define Nrows 8192
#define TILES 64          // 8192 / 128
#define NBLK  2080        // 64*65/2 triangular tiles
#define GRID2 2072        // k_main grid; blocks 0..7 run a second tile

// ===================== device scratch ====================================
__device__ __align__(16) __half g_xh[4][Nrows][64];
__device__ float g_sq[Nrows];
__device__ float g_spart[128][Ccls];
__device__ float g_tpart[128][Ccls];
__device__ int   g_cpart[128][Ccls];
__device__ __align__(16) float g_vpartT[256][256]; // TRANSPOSED column sums
__device__ float g_qpart[256];
__device__ float g_sscale[Ccls];
__device__ float g_tscale[Ccls];
__device__ float g_expC;              // log2e/(4*bw_raw)  (exp2 domain)
__device__ float g_invcount;
__device__ unsigned g_ctr;            // last-block counter (monotonic)

// ---------------- helpers -------------------------------------------------
__device__ __forceinline__ void mma_f16(float* d, const uint32_t* a, const uint32_t* b) {
    asm volatile(
        "mma.sync.aligned.m16n8k16.row.col.f32.f16.f16.f32 "
        "{%0,%1,%2,%3}, {%4,%5,%6,%7}, {%8,%9}, {%0,%1,%2,%3};"
        : "+f"(d[0]), "+f"(d[1]), "+f"(d[2]), "+f"(d[3])
        : "r"(a[0]), "r"(a[1]), "r"(a[2]), "r"(a[3]), "r"(b[0]), "r"(b[1]));
}
__device__ __forceinline__ void ldsm_x4(uint32_t* r, uint32_t addr) {
    asm volatile("ldmatrix.sync.aligned.m8n8.x4.shared.b16 {%0,%1,%2,%3}, [%4];"
        : "=r"(r[0]), "=r"(r[1]), "=r"(r[2]), "=r"(r[3]) : "r"(addr));
}
__device__ __forceinline__ uint32_t smem_u32(const void* p) {
    return (uint32_t)__cvta_generic_to_shared(p);
}
__device__ __forceinline__ float ex2(float x) {
    float r;
    asm("ex2.approx.ftz.f32 %0, %1;" : "=f"(r) : "f"(x));
    return r;
}
#define MBAR_INIT(mbar, cnt) \
    asm volatile("mbarrier.init.shared.b64 [%0], %1;" \
                 :: "r"((uint32_t)(mbar)), "r"((uint32_t)(cnt)) : "memory")
#define MBAR_EXPECT_TX(mbar, bytes) \
    asm volatile("mbarrier.arrive.expect_tx.shared.b64 _, [%0], %1;" \
                 :: "r"((uint32_t)(mbar)), "r"((uint32_t)(bytes)) : "memory")
#define BULK_G2S(dst, src, bytes, mbar) \
    asm volatile("cp.async.bulk.shared::cluster.global.mbarrier::complete_tx::bytes " \
                 "[%0], [%1], %2, [%3];" \
                 :: "r"((uint32_t)(dst)), "l"(src), "r"((uint32_t)(bytes)), \
                    "r"((uint32_t)(mbar)) : "memory")
#define MBAR_WAIT(mbar, parity) do {                                             \
    uint32_t _m = (uint32_t)(mbar); uint32_t _p = (uint32_t)(parity);            \
    uint32_t _done;                                                              \
    asm volatile("{\n\t.reg .pred p;\n\t"                                        \
        "mbarrier.try_wait.parity.acquire.cta.shared::cta.b64 p, [%1], %2;\n\t"  \
        "selp.b32 %0, 1, 0, p;\n\t}" : "=r"(_done) : "r"(_m), "r"(_p) : "memory"); \
    if (!_done) {                                                                \
        asm volatile("{\n\t.reg .pred P1;\n\t"                                   \
            "W_%=:\n\t"                                                          \
            "mbarrier.try_wait.parity.acquire.cta.shared::cta.b64 P1, [%0], %1, 0x989680;\n\t" \
            "@P1 bra.uni D_%=;\n\tbra.uni W_%=;\n\tD_%=:\n\t}"                   \
            :: "r"(_m), "r"(_p) : "memory");                                     \
    }                                                                            \
} while (0)

// ---------------- kernel 1: rows + stats + (last block) finalize ----------
// 256 blocks x 256 threads; block = 32 rows (R13-proven).
__global__ void k_row(const float* __restrict__ src,
                      const float* __restrict__ tgt,
                      const float* __restrict__ slab,
                      const float* __restrict__ tlog,
                      float* __restrict__ out) {
    __shared__ float scol[8][256];
    __shared__ float bs[8];
    __shared__ int   lastFlag;
    int tid = threadIdx.x;
    int w = tid >> 5, lane = tid & 31;
    int bid = blockIdx.x;

    if (w == 0) {
        int r = bid * 32 + lane;
        float val[Ccls];
        int bx = 0;
        if (bid < 128) {
            #pragma unroll
            for (int c = 0; c < Ccls; c++) val[c] = slab[(size_t)r * Ccls + c];
        } else {
            int rr = r - Bsz;
            float best = -1.f;
            #pragma unroll
            for (int c = 0; c < Ccls; c++) {
                val[c] = tlog[(size_t)rr * Ccls + c];
                if (val[c] > best) { best = val[c]; bx = c; }
            }
        }
        #pragma unroll
        for (int c = 0; c < Ccls; c++) {
            float x = val[c];
            #pragma unroll
            for (int o = 16; o; o >>= 1) x += __shfl_xor_sync(0xffffffffu, x, o);
            int cc = __popc(__ballot_sync(0xffffffffu, bx == c));
            if (lane == 0) {
                if (bid < 128) g_spart[bid][c] = x;
                else { g_tpart[bid - 128][c] = x; g_cpart[bid - 128][c] = cc; }
            }
        }
    }

    float2 colacc[4];
    #pragma unroll
    for (int i = 0; i < 4; i++) colacc[i] = make_float2(0.f, 0.f);
    float wsq = 0.f;
    int c0 = 2 * lane;
    int uu = c0 >> 3, oo = c0 & 7;
    #pragma unroll
    for (int k = 0; k < 4; k++) {
        int row = bid * 32 + w * 4 + k;
        const float* p = (row < Bsz) ? src + (size_t)row * Dd
                                     : tgt + (size_t)(row - Bsz) * Dd;
        int rx = row & 7;
        int sw = (((uu ^ rx) << 3) | oo);
        float s = 0.f;
        #pragma unroll
        for (int i = 0; i < 4; i++) {
            float2 v = *(const float2*)(p + c0 + 64 * i);
            s += v.x * v.x + v.y * v.y;
            colacc[i].x += v.x; colacc[i].y += v.y;
            *(__half2*)&g_xh[i][row][sw] = __floats2half2_rn(v.x, v.y);
        }
        #pragma unroll
        for (int o = 16; o; o >>= 1) s += __shfl_xor_sync(0xffffffffu, s, o);
        if (lane == 0) { g_sq[row] = s; wsq += s; }
    }
    #pragma unroll
    for (int i = 0; i < 4; i++) *(float2*)&scol[w][c0 + 64 * i] = colacc[i];
    if (lane == 0) bs[w] = wsq;
    __syncthreads();
    float cs = 0.f;
    #pragma unroll
    for (int ww = 0; ww < 8; ww++) cs += scol[ww][tid];
    g_vpartT[tid][bid] = cs;
    if (tid == 0) {
        float tot = 0.f;
        #pragma unroll
        for (int i = 0; i < 8; i++) tot += bs[i];
        g_qpart[bid] = tot;
    }

    __threadfence();
    if (tid == 0) {
        unsigned old = atomicAdd(&g_ctr, 1u);
        lastFlag = (((old + 1u) & 255u) == 0u);
    }
    __syncthreads();
    if (!lastFlag) return;

    __shared__ float red[256];
    __shared__ float ssumS[Ccls];
    __shared__ int   cntS[Ccls];
    int t = tid;
    if (t < Ccls) {
        float ss = 0.f, ts = 0.f; int cc = 0;
        #pragma unroll 4
        for (int b2 = 0; b2 < 128; b2++) {
            ss += g_spart[b2][t];
            ts += g_tpart[b2][t];
            cc += g_cpart[b2][t];
        }
        ssumS[t] = ss; cntS[t] = cc;
        bool mask = (ss > 0.f) && (cc > 0);
        g_sscale[t] = mask ? (1.f / ss) : 0.f;
        float te = (ts == 0.f) ? 100.f : ts;
        g_tscale[t] = mask ? (-1.f / te) : 0.f;
    }
    float v = 0.f;
    {
        const float4* vp = (const float4*)&g_vpartT[t][0];
        #pragma unroll 16
        for (int i = 0; i < 64; i++) {
            float4 x = vp[i];
            v += (x.x + x.y) + (x.z + x.w);
        }
    }
    red[t] = v * v;
    __syncthreads();
    for (int s = 128; s; s >>= 1) { if (t < s) red[t] += red[t + s]; __syncthreads(); }
    float VV = red[0];
    __syncthreads();
    red[t] = g_qpart[t];
    __syncthreads();
    for (int s = 128; s; s >>= 1) { if (t < s) red[t] += red[t + s]; __syncthreads(); }
    if (t == 0) {
        int count = 0;
        for (int c = 0; c < Ccls; c++)
            if (ssumS[c] > 0.f && cntS[c] > 0) count++;
        float S = red[0];
        float sum_l2 = 2.f * (float)Nrows * S - 2.f * VV;
        float nf = (float)Nrows;
        float bw_raw = sum_l2 / (nf * nf - nf);
        g_expC = 1.44269504088896f / (4.f * bw_raw);
        g_invcount = (count > 0) ? 1.f / (float)count : 0.f;
        out[0] = 0.f;
    }
}

// ---------------- kernel 2: fp16 mma pairwise GEMM + MMD epilogue ---------
// R13-proven body; grid = 2072, blocks 0..7 loop a second tile (2072+bid).
// SIX mbarriers (two sets of 3), all initialized ONCE at kernel start;
// iteration i uses set i&1. No mid-kernel barrier reset -> no proxy hazard.
#define NSTAGE  3
#define STAGEB  32768
#define OFF_BUF 0
#define OFF_MBAR (NSTAGE * STAGEB)      // 6 x 8B (two sets)
#define OFF_UPH (OFF_MBAR + 64)         // [128][24] halves, 48B stride
#define OFF_UQH (OFF_UPH + 128 * 48)
#define OFF_SQP (OFF_UQH + 128 * 48)
#define OFF_SQQ (OFF_SQP + 512)
#define OFF_RED (OFF_SQQ + 512)
#define SMEM_DYN (OFF_RED + 64)

__global__ void __launch_bounds__(256, 2) k_main(
    const float* __restrict__ slab, const float* __restrict__ tlog,
    float* __restrict__ out)
{
    extern __shared__ char sm[];
    float* sqP = (float*)(sm + OFF_SQP);
    float* sqQ = (float*)(sm + OFF_SQQ);
    float* red = (float*)(sm + OFF_RED);
    uint32_t smb = smem_u32(sm);

    int tid = threadIdx.x;
    int w = tid >> 5, lane = tid & 31;
    int g = lane >> 2, t4 = lane & 3;
    int wr = w >> 2, wc = w & 3;

    // ---- init ALL SIX mbarriers once (launch-boundary proxy-safe) ----
    if (tid == 0) {
        #pragma unroll
        for (int s = 0; s < 2 * NSTAGE; s++) MBAR_INIT(smb + OFF_MBAR + 8 * s, 1);
    }
    __syncthreads();

    // per-lane ldmatrix geometry (tile-invariant)
    uint32_t rx = (uint32_t)(lane & 7);
    uint32_t baseA = (uint32_t)((wr * 64 + (lane & 7) + ((lane >> 3) & 1) * 8) * 128);
    uint32_t hiA = (uint32_t)(lane >> 4);
    uint32_t baseB = (uint32_t)(16384 + (wc * 32 + (lane & 7) + ((lane >> 4) & 1) * 8) * 128);
    uint32_t hiB = (uint32_t)((lane >> 3) & 1);
    uint32_t rowuB = (uint32_t)(wc * 32 + (lane & 7) + ((lane >> 4) & 1) * 8);
    uint32_t addrUB = smb + OFF_UQH + rowuB * 48u + ((uint32_t)((lane >> 3) & 1)) * 16u;

    float total = 0.f;
    int iter = 0;

    for (int tile = blockIdx.x; tile < NBLK; tile += GRID2, iter++) {
        uint32_t mbase = smb + OFF_MBAR + (uint32_t)(iter & 1) * 24u;
        if (iter > 0) __syncthreads();    // prev epilogue smem reads complete

        // triangular decode (bi <= bj)
        int bi = (int)((2.f * TILES + 1.f -
                        sqrtf((float)((2 * TILES + 1) * (2 * TILES + 1) - 8 * tile))) * 0.5f);
        if (bi < 0) bi = 0; if (bi > TILES - 1) bi = TILES - 1;
        while (bi > 0 && bi * TILES - bi * (bi - 1) / 2 > tile) bi--;
        while ((bi + 1) * TILES - (bi + 1) * bi / 2 <= tile) bi++;
        int bj = bi + (tile - (bi * TILES - bi * (bi - 1) / 2));
        int p0 = bi * 128, q0 = bj * 128;

        // ---- prefetch chunks 0-2 ----
        if (tid == 0) {
            #pragma unroll
            for (int s = 0; s < NSTAGE; s++) {
                uint32_t mb = mbase + 8 * s;
                uint32_t dst = smb + OFF_BUF + s * STAGEB;
                MBAR_EXPECT_TX(mb, 2 * 16384);
                BULK_G2S(dst,          &g_xh[s][p0][0], 16384, mb);
                BULK_G2S(dst + 16384u, &g_xh[s][q0][0], 16384, mb);
            }
        }

        // ---- stage u vectors as fp16 (x256) + squared norms ----
        {
            int half_ = tid >> 7;
            int j = tid & 127;
            int rr = (half_ ? q0 : p0) + j;
            uint32_t uoff = (half_ ? OFF_UQH : OFF_UPH) + (uint32_t)j * 48u;
            __half2* d = (__half2*)(sm + uoff);
            if (half_) sqQ[j] = g_sq[rr]; else sqP[j] = g_sq[rr];
            const float* base;
            const float* scl;
            if (rr < Bsz) { base = slab + (size_t)rr * Ccls; scl = g_sscale; }
            else          { base = tlog + (size_t)(rr - Bsz) * Ccls; scl = g_tscale; }
            #pragma unroll
            for (int c2 = 0; c2 < 5; c2++) {
                float a = base[2 * c2]     * scl[2 * c2]     * 256.f;
                float e = base[2 * c2 + 1] * scl[2 * c2 + 1] * 256.f;
                d[c2] = __floats2half2_rn(a, e);
            }
            #pragma unroll
            for (int c2 = 5; c2 < 12; c2++) d[c2] = __floats2half2_rn(0.f, 0.f);
        }

        float acc[16][4];
        #pragma unroll
        for (int i = 0; i < 16; i++)
            #pragma unroll
            for (int j = 0; j < 4; j++) acc[i][j] = 0.f;

        // ---- mainloop: 4 K-chunks, compile-time stage/phase ----
        #pragma unroll
        for (int ch = 0; ch < 4; ch++) {
            const int st = ch % NSTAGE;
            const int ph = ch / NSTAGE;
            MBAR_WAIT(mbase + 8 * st, ph);

            uint32_t bufb = smb + OFF_BUF + st * STAGEB;
            uint32_t fA[2][4][4];
            uint32_t fB[2][4][2];
            {
                uint32_t ka = ((hiA ^ rx) << 4);
                uint32_t kb = ((hiB ^ rx) << 4);
                #pragma unroll
                for (int mi = 0; mi < 4; mi++)
                    ldsm_x4(fA[0][mi], bufb + baseA + mi * 2048u + ka);
                #pragma unroll
                for (int np = 0; np < 2; np++)
                    ldsm_x4(&fB[0][2 * np][0], bufb + baseB + np * 2048u + kb);
            }
            #pragma unroll
            for (int ks = 0; ks < 4; ks++) {
                int cur = ks & 1;
                if (ks < 3) {
                    uint32_t kn = (uint32_t)((ks + 1) << 1);
                    uint32_t ka = (((kn | hiA) ^ rx) << 4);
                    uint32_t kb = (((kn | hiB) ^ rx) << 4);
                    #pragma unroll
                    for (int mi = 0; mi < 4; mi++)
                        ldsm_x4(fA[cur ^ 1][mi], bufb + baseA + mi * 2048u + ka);
                    #pragma unroll
                    for (int np = 0; np < 2; np++)
                        ldsm_x4(&fB[cur ^ 1][2 * np][0], bufb + baseB + np * 2048u + kb);
                }
                #pragma unroll
                for (int mi = 0; mi < 4; mi++)
                    #pragma unroll
                    for (int ni = 0; ni < 4; ni++)
                        mma_f16(acc[mi * 4 + ni], fA[cur][mi], fB[cur][ni]);
            }
            if (ch == 0) {
                __syncthreads();
                if (tid == 0) {
                    uint32_t mb = mbase + 0;
                    uint32_t dst = smb + OFF_BUF + 0;
                    MBAR_EXPECT_TX(mb, 2 * 16384);
                    BULK_G2S(dst,          &g_xh[3][p0][0], 16384, mb);
                    BULK_G2S(dst + 16384u, &g_xh[3][q0][0], 16384, mb);
                }
            }
        }

        // ---- epilogue: W via tensor cores + gaussian kernel (exp2) ----
        const float Ce = g_expC;
        const float twoCe = 2.f * Ce;
        const float scale = g_invcount * ((bi == bj) ? 1.f : 2.f) * (1.f / 65536.f);
        float partial = 0.f;

        uint32_t fuB[2][4];
        ldsm_x4(fuB[0], addrUB);
        ldsm_x4(fuB[1], addrUB + 16u * 48u);

        #pragma unroll
        for (int mi = 0; mi < 4; mi++) {
            int r0 = wr * 64 + mi * 16 + g;
            int r1 = r0 + 8;
            float spC0 = sqP[r0] * Ce, spC1 = sqP[r1] * Ce;

            uint32_t fuA[4];
            {
                uint32_t rowuA = (uint32_t)(wr * 64 + mi * 16 + (lane & 7) + ((lane >> 3) & 1) * 8);
                ldsm_x4(fuA, smb + OFF_UPH + rowuA * 48u + ((uint32_t)(lane >> 4)) * 16u);
            }
            float wacc[4][4];
            #pragma unroll
            for (int ni = 0; ni < 4; ni++) {
                #pragma unroll
                for (int j = 0; j < 4; j++) wacc[ni][j] = 0.f;
                mma_f16(wacc[ni], fuA, &fuB[ni >> 1][(ni & 1) * 2]);
            }
            #pragma unroll
            for (int ni = 0; ni < 4; ni++) {
                float* a = acc[mi * 4 + ni];
                float* wa = wacc[ni];
                int cbx = wc * 32 + ni * 8 + 2 * t4;
                float2 sv = *(float2*)&sqQ[cbx];
                float svCx = sv.x * Ce, svCy = sv.y * Ce;
                float t, z, z2, z4, z8;
                t = fminf(fmaf(a[0], twoCe, -(spC0 + svCx)), 0.f);
                z = ex2(t); z2 = z * z; z4 = z2 * z2; z8 = z4 * z4;
                partial = fmaf(wa[0], z + z2 + z4 + z8 + z8 * z8, partial);
                t = fminf(fmaf(a[1], twoCe, -(spC0 + svCy)), 0.f);
                z = ex2(t); z2 = z * z; z4 = z2 * z2; z8 = z4 * z4;
                partial = fmaf(wa[1], z + z2 + z4 + z8 + z8 * z8, partial);
                t = fminf(fmaf(a[2], twoCe, -(spC1 + svCx)), 0.f);
                z = ex2(t); z2 = z * z; z4 = z2 * z2; z8 = z4 * z4;
                partial = fmaf(wa[2], z + z2 + z4 + z8 + z8 * z8, partial);
                t = fminf(fmaf(a[3], twoCe, -(spC1 + svCy)), 0.f);
                z = ex2(t); z2 = z * z; z4 = z2 * z2; z8 = z4 * z4;
                partial = fmaf(wa[3], z + z2 + z4 + z8 + z8 * z8, partial);
            }
        }
        total = fmaf(partial, scale, total);
    }

    // ---- final reduction + single atomic per CTA ----
    #pragma unroll
    for (int o = 16; o; o >>= 1) total += __shfl_xor_sync(0xffffffffu, total, o);
    if (lane == 0) red[w] = total;
    __syncthreads();
    if (tid == 0) {
        float s = 0.f;
        #pragma unroll
        for (int i = 0; i < 8; i++) s += red[i];
        atomicAdd(out, s);
    }
}

// ---------------- launcher ------------------------------------------------
extern "C" void kernel_launch(void* const* d_in, const int* in_sizes, int n_in,
                              void* d_out, int out_size) {
    const float* src  = (const float*)d_in[0];
    const float* tgt  = (const float*)d_in[1];
    const float* slab = (const float*)d_in[2];
    const float* tlog = (const float*)d_in[3];
    float* out = (float*)d_out;

    static int configured = 0;
    if (!configured) {
        cudaFuncSetAttribute(k_main, cudaFuncAttributeMaxDynamicSharedMemorySize, SMEM_DYN);
        configured = 1;
    }

    k_row<<<256, 256>>>(src, tgt, slab, tlog, out);
    k_main<<<GRID2, 256, SMEM_DYN>>>(slab, tlog, out);
}